// round 7
// baseline (speedup 1.0000x reference)
#include <cuda_runtime.h>
#include <math.h>

// BATCH=128, SEQ_LEN=4096, HIDDEN=512, WINDOW=7 (W2=49), GRID=256
#define HIDDEN   512
#define WINDOW   7
#define W2       (WINDOW * WINDOW)
#define NTHREADS 1024
#define NWARPS   (NTHREADS / 32)    // 32
#define MAXW     2                  // ceil(49/32)

typedef unsigned long long u64;

// packed fp32x2 FMA (sm_100+): d = a*b + d, elementwise on two fp32 lanes
__device__ __forceinline__ void fma2(u64 &d, u64 a, u64 b) {
    asm("fma.rn.f32x2 %0, %1, %2, %0;" : "+l"(d) : "l"(a), "l"(b));
}
__device__ __forceinline__ float f2sum(u64 d) {
    float lo, hi;
    asm("mov.b64 {%0, %1}, %2;" : "=f"(lo), "=f"(hi) : "l"(d));
    return lo + hi;
}
__device__ __forceinline__ u64 bcast2(float e) {
    u64 r;
    asm("mov.b64 %0, {%1, %1};" : "=l"(r) : "f"(e));
    return r;
}

__global__ __launch_bounds__(NTHREADS, 1)
void hilbert_attn_kernel(const float* __restrict__ q,      // (B,1,H)
                         const float* __restrict__ k,      // (B,S,H)
                         const float* __restrict__ v,      // (B,S,H)
                         const int*   __restrict__ qpos,   // (B,)
                         const float* __restrict__ dscale, // ()
                         const float* __restrict__ lbias,  // (W2,)
                         const int*   __restrict__ hcoords,// (MAX_SEQ,2)
                         const int*   __restrict__ hinv,   // (GRID,GRID)
                         float*       __restrict__ out,    // (B,H)
                         int S, int grid_n)
{
    const int b    = blockIdx.x;
    const int tid  = threadIdx.x;
    const int wid  = tid >> 5;
    const int lane = tid & 31;
    const unsigned FULL = 0xffffffffu;

    extern __shared__ u64 s_part8[];          // 32 slots * 256 u64 = 64 KB
    __shared__ float s_esum[NWARPS];

    // ---- q slice into registers as packed f32x2 pairs ----
    ulonglong2 qv2[4];
    {
        const ulonglong2* qg = reinterpret_cast<const ulonglong2*>(q + (size_t)b * HIDDEN);
        #pragma unroll
        for (int c = 0; c < 4; ++c) qv2[c] = qg[c * 32 + lane];
    }

    // ---- warp-autonomous window resolution (no block barriers) ----
    const int p   = qpos[b];
    const int qx  = hcoords[2 * p];
    const int qy  = hcoords[2 * p + 1];
    const float scale = dscale[0];

    int wA = lane;
    int dxA = wA / WINDOW - (WINDOW / 2);
    int dyA = wA % WINDOW - (WINDOW / 2);
    int nxA = qx + dxA, nyA = qy + dyA;
    bool ingA = (nxA >= 0) & (nxA < grid_n) & (nyA >= 0) & (nyA < grid_n);
    int posA = ingA ? hinv[nxA * grid_n + nyA] : -1;
    bool vA = ingA && (posA >= 0) && (posA < S);

    int wB = lane + 32;
    bool inB = (wB < W2);
    int dxB = inB ? (wB / WINDOW - (WINDOW / 2)) : 0;
    int dyB = inB ? (wB % WINDOW - (WINDOW / 2)) : 0;
    int nxB = qx + dxB, nyB = qy + dyB;
    bool ingB = inB & (nxB >= 0) & (nxB < grid_n) & (nyB >= 0) & (nyB < grid_n);
    int posB = ingB ? hinv[nxB * grid_n + nyB] : -1;
    bool vB = ingB && (posB >= 0) && (posB < S);

    const unsigned m0 = __ballot_sync(FULL, vA);
    const unsigned m1 = __ballot_sync(FULL, vB);

    // This warp's two windows: w = wid and w = wid + 32 (latter only wid < 17)
    int   mypos[MAXW];
    float myval[MAXW];
    float mylw[MAXW];
    {
        int p0 = __shfl_sync(FULL, posA, wid);
        bool ok0 = (m0 >> wid) & 1u;
        mypos[0] = ok0 ? p0 : 0;
        myval[0] = ok0 ? 1.0f : 0.0f;
        float lw0 = 0.0f;
        if (ok0) {
            int c = __popc(m0 & ((2u << wid) - 1u)) - 1;
            int dist = abs(wid / WINDOW - 3) + abs(wid % WINDOW - 3);
            lw0 = __logf(__expf(-(float)dist * scale) + __ldg(lbias + c) + 1e-8f);
        }
        mylw[0] = lw0;

        int p1 = __shfl_sync(FULL, posB, wid);
        bool ok1 = (wid < W2 - 32) && ((m1 >> wid) & 1u);
        mypos[1] = ok1 ? p1 : 0;
        myval[1] = ok1 ? 1.0f : 0.0f;
        float lw1 = 0.0f;
        if (ok1) {
            int w = wid + 32;
            int c = __popc(m0) + __popc(m1 & ((2u << wid) - 1u)) - 1;
            int dist = abs(w / WINDOW - 3) + abs(w % WINDOW - 3);
            lw1 = __logf(__expf(-(float)dist * scale) + __ldg(lbias + c) + 1e-8f);
        }
        mylw[1] = lw1;
    }

    const float* kb = k + (size_t)b * S * HIDDEN;
    const float* vb = v + (size_t)b * S * HIDDEN;
    const ulonglong2* kr[MAXW];
    const ulonglong2* vr[MAXW];
    #pragma unroll
    for (int j = 0; j < MAXW; ++j) {
        kr[j] = reinterpret_cast<const ulonglong2*>(kb + (size_t)mypos[j] * HIDDEN);
        vr[j] = reinterpret_cast<const ulonglong2*>(vb + (size_t)mypos[j] * HIDDEN);
    }

    // ---- dots: packed f32x2 FMAs, chunk-major, unconditional loads ----
    u64 d2[MAXW] = {0ULL, 0ULL};
    #pragma unroll
    for (int c = 0; c < 4; ++c) {
        ulonglong2 kk[MAXW];
        #pragma unroll
        for (int j = 0; j < MAXW; ++j) kk[j] = kr[j][c * 32 + lane];
        #pragma unroll
        for (int j = 0; j < MAXW; ++j) {
            fma2(d2[j], kk[j].x, qv2[c].x);
            fma2(d2[j], kk[j].y, qv2[c].y);
        }
    }
    float d[MAXW];
    #pragma unroll
    for (int j = 0; j < MAXW; ++j) d[j] = f2sum(d2[j]);

    #pragma unroll
    for (int off = 16; off > 0; off >>= 1) {
        #pragma unroll
        for (int j = 0; j < MAXW; ++j)
            d[j] += __shfl_xor_sync(FULL, d[j], off);
    }

    // ---- unnormalized exp weights (0 for invalid windows) ----
    const float inv_sqrt_h = 0.04419417382415922f; // 1/sqrt(512)
    float e[MAXW];
    float esum = 0.0f;
    u64 e2[MAXW];
    #pragma unroll
    for (int j = 0; j < MAXW; ++j) {
        e[j] = myval[j] * __expf(d[j] * inv_sqrt_h + mylw[j]);
        esum += e[j];
        e2[j] = bcast2(e[j]);
    }

    // ---- weighted V accumulation: packed f32x2 FMAs ----
    u64 acc2[8];
    #pragma unroll
    for (int i = 0; i < 8; ++i) acc2[i] = 0ULL;
    #pragma unroll
    for (int c = 0; c < 4; ++c) {
        ulonglong2 vv[MAXW];
        #pragma unroll
        for (int j = 0; j < MAXW; ++j) vv[j] = vr[j][c * 32 + lane];
        #pragma unroll
        for (int j = 0; j < MAXW; ++j) {
            fma2(acc2[2 * c],     e2[j], vv[j].x);
            fma2(acc2[2 * c + 1], e2[j], vv[j].y);
        }
    }

    // ---- single-stage cross-warp reduction: 32 slots, one barrier ----
    {
        ulonglong2* sp = reinterpret_cast<ulonglong2*>(s_part8 + wid * (HIDDEN / 2));
        #pragma unroll
        for (int c = 0; c < 4; ++c)
            sp[c * 32 + lane] = make_ulonglong2(acc2[2 * c], acc2[2 * c + 1]);
        if (lane == 0) s_esum[wid] = esum;
    }
    __syncthreads();

    // ---- final 32-slot sum + normalize (threads 0..511) ----
    if (tid < HIDDEN) {
        const float* s_part_f = reinterpret_cast<const float*>(s_part8);
        float num = 0.0f;
        #pragma unroll
        for (int s = 0; s < NWARPS; ++s) num += s_part_f[s * HIDDEN + tid];
        float den = 0.0f;
        #pragma unroll
        for (int s = 0; s < NWARPS; ++s) den += s_esum[s];
        out[(size_t)b * HIDDEN + tid] = num / den;
    }
}

extern "C" void kernel_launch(void* const* d_in, const int* in_sizes, int n_in,
                              void* d_out, int out_size)
{
    const float* q       = (const float*)d_in[0];
    const float* k       = (const float*)d_in[1];
    const float* v       = (const float*)d_in[2];
    const int*   qpos    = (const int*)d_in[3];
    const float* dscale  = (const float*)d_in[4];
    const float* lbias   = (const float*)d_in[5];
    const int*   hcoords = (const int*)d_in[6];
    const int*   hinv    = (const int*)d_in[7];
    float*       out     = (float*)d_out;

    int B = in_sizes[3];                      // 128
    int H = in_sizes[0] / B;                  // 512
    int S = in_sizes[1] / (B * H);            // 4096
    int inv_elems = in_sizes[7];              // grid*grid
    int grid_n = 1;
    while (grid_n * grid_n < inv_elems) grid_n <<= 1;  // 256

    const int dyn_smem = NWARPS * HIDDEN * (int)sizeof(float);  // 64 KB
    cudaFuncSetAttribute(hilbert_attn_kernel,
                         cudaFuncAttributeMaxDynamicSharedMemorySize, dyn_smem);

    hilbert_attn_kernel<<<B, NTHREADS, dyn_smem>>>(q, k, v, qpos, dscale, lbias,
                                                   hcoords, hinv, out, S, grid_n);
}